// round 16
// baseline (speedup 1.0000x reference)
#include <cuda_runtime.h>
#include <cuda_bf16.h>
#include <cuda_fp16.h>
#include <math.h>
#include <stdint.h>

#define NSEQ 8192
#define DMODEL 256

typedef unsigned long long u64;

// ---------------------------------------------------------------------------
// Warp-level tensor-core + cp.async primitives (sm_80+, valid for sm_103 PTX)
// ---------------------------------------------------------------------------
__device__ __forceinline__ uint32_t smem_to_u32(const void* p) {
    uint32_t a;
    asm("{ .reg .u64 t; cvta.to.shared.u64 t, %1; cvt.u32.u64 %0, t; }" : "=r"(a) : "l"(p));
    return a;
}
__device__ __forceinline__ void ldmx4(uint32_t addr, uint32_t r[4]) {
    asm volatile("ldmatrix.sync.aligned.m8n8.x4.shared.b16 {%0,%1,%2,%3}, [%4];"
                 : "=r"(r[0]), "=r"(r[1]), "=r"(r[2]), "=r"(r[3]) : "r"(addr));
}
__device__ __forceinline__ void ldmx4t(uint32_t addr, uint32_t r[4]) {
    asm volatile("ldmatrix.sync.aligned.m8n8.x4.trans.shared.b16 {%0,%1,%2,%3}, [%4];"
                 : "=r"(r[0]), "=r"(r[1]), "=r"(r[2]), "=r"(r[3]) : "r"(addr));
}
// fp16 MMA, fp32 accum
__device__ __forceinline__ void mma16816h(float* c, const uint32_t* a, uint32_t b0, uint32_t b1) {
    asm volatile(
        "mma.sync.aligned.m16n8k16.row.col.f32.f16.f16.f32 "
        "{%0,%1,%2,%3},{%4,%5,%6,%7},{%8,%9},{%0,%1,%2,%3};"
        : "+f"(c[0]), "+f"(c[1]), "+f"(c[2]), "+f"(c[3])
        : "r"(a[0]), "r"(a[1]), "r"(a[2]), "r"(a[3]), "r"(b0), "r"(b1));
}
__device__ __forceinline__ uint32_t pack_f16(float lo, float hi) {
    uint32_t r;
    asm("cvt.rn.f16x2.f32 %0, %1, %2;" : "=r"(r) : "f"(hi), "f"(lo));
    return r;
}
__device__ __forceinline__ void cp16(uint32_t dst, const void* src) {
    asm volatile("cp.async.cg.shared.global [%0], [%1], 16;" :: "r"(dst), "l"(src) : "memory");
}
#define CP_COMMIT()  asm volatile("cp.async.commit_group;" ::: "memory")
#define CP_WAIT0()   asm volatile("cp.async.wait_group 0;" ::: "memory")
#define BAR_PAIR(id) asm volatile("bar.sync %0, 64;" :: "r"(id) : "memory")

// ---------------------------------------------------------------------------
// Schedule: splits per row-tile; sum over rt=0..63 equals 296 = 2 x 148 SMs.
// ---------------------------------------------------------------------------
__host__ __device__ __forceinline__ int nsplits(int rt) { return ((rt + 1) >> 3) + 1; }
#define GRID_FLASH 296

// ---------------------------------------------------------------------------
// Device globals (no allocs allowed)
// ---------------------------------------------------------------------------
__device__ __half gQ [NSEQ * DMODEL];                // fp16, pre-scaled by 1/16
__device__ __half gKh[NSEQ * DMODEL];                // single fp16 plane
__device__ __half gV [NSEQ * DMODEL];                // single fp16 plane
__device__ __half gW [3 * DMODEL * DMODEL];          // fp16 weights (z-major)
__device__ float g_Opart[GRID_FLASH * 128 * 256];    // dense: pidx = blockIdx.x
__device__ float g_lpart[GRID_FLASH * 2 * 128];      // 2 key-half slots per CTA
__device__ int   g_mask_kind;

// Read 2 consecutive mask values at even element index.
__device__ __forceinline__ float2 read_mask2(const void* m, int kind, size_t idx) {
    float2 r;
    if (kind == 0) {
        float2 v = *(const float2*)((const float*)m + idx);
        r.x = (v.x != 0.f) ? 1.f : 0.f; r.y = (v.y != 0.f) ? 1.f : 0.f;
    } else if (kind == 2) {
        unsigned short v = *(const unsigned short*)((const unsigned char*)m + idx);
        r.x = (v & 0xFFu) ? 1.f : 0.f; r.y = (v >> 8) ? 1.f : 0.f;
    } else if (kind == 1) {
        int2 v = *(const int2*)((const int*)m + idx);
        r.x = (v.x != 0) ? 1.f : 0.f; r.y = (v.y != 0) ? 1.f : 0.f;
    } else {
        unsigned v = *(const unsigned*)((const unsigned short*)m + idx);
        r.x = (v & 0xFFFFu) ? 1.f : 0.f; r.y = (v >> 16) ? 1.f : 0.f;
    }
    return r;
}

// ---------------------------------------------------------------------------
// Weight conversion + mask dtype detection fused (block 0 detects first).
// ---------------------------------------------------------------------------
__global__ void __launch_bounds__(256)
w_convert_kernel(const float* __restrict__ Wq, const float* __restrict__ Wk,
                 const float* __restrict__ Wv, const unsigned int* __restrict__ mw) {
    if (blockIdx.x == 0) {
        __shared__ int flags;
        if (threadIdx.x == 0) flags = 0;
        __syncthreads();
        int f = 0;
        for (int i = threadIdx.x; i < 2048; i += blockDim.x) {
            unsigned v = mw[i];
            if (v == 0u) continue;
            if (v == 0x3F803F80u || v == 0x00003F80u) f |= 2;
            else if (v == 0x3C003C00u || v == 0x00003C00u || v == 0x3C000000u) f |= 2;
            else if (v == 0x3F800000u) f |= 1;
            else if (v == 1u) f |= 8;
            else f |= 4;
        }
        atomicOr(&flags, f);
        __syncthreads();
        if (threadIdx.x == 0) {
            int fl = flags, kind;
            if      (fl & 2) kind = 3;      // 16-bit
            else if (fl & 1) kind = 0;      // f32
            else if (fl & 4) kind = 2;      // u8
            else if (fl & 8) kind = 1;      // i32
            else             kind = 0;
            g_mask_kind = kind;
        }
    }

    const int z = blockIdx.x;
    const float* W = (z == 0) ? Wq : ((z == 1) ? Wk : Wv);
    __half* dst = gW + (size_t)z * DMODEL * DMODEL;
    for (int i = threadIdx.x; i < DMODEL * DMODEL / 4; i += 256) {
        float4 v = *(const float4*)(W + i * 4);
        *(uint32_t*)(dst + i * 4)     = pack_f16(v.x, v.y);
        *(uint32_t*)(dst + i * 4 + 2) = pack_f16(v.z, v.w);
    }
}

// ---------------------------------------------------------------------------
// Tensor-core QKV, 512 threads (16 warps): C[128 x 256] = (Xh + Xl) @ W^T.
// Same 192KB smem layout as R12 (proven); only warp mapping changes:
// rg = w&7 owns rows 16*rg, h = w>>3 owns 64-col half of the 128-col chunk.
// Warps/SMSP 2 -> 4 for latency hiding. Arithmetic per output bit-identical.
// ---------------------------------------------------------------------------
#define QOFF_XH 0
#define QOFF_XL 65536
#define QOFF_WB 131072
#define QKV_SMEM 196608

__global__ void __launch_bounds__(512, 1)
qkv_tc_kernel(const float* __restrict__ X) {
    extern __shared__ char smem[];
    const int tid = threadIdx.x;
    const int w = tid >> 5, lane = tid & 31;
    const int g = lane >> 2, t4 = lane & 3;
    const int rg = w & 7;            // rows 16*rg .. 16*rg+15
    const int h  = w >> 3;           // 64-col half within the 128-col chunk
    const int m0 = blockIdx.x * 128;
    const int z = blockIdx.y;
    const uint32_t sb = smem_to_u32(smem);

    const __half* Wsrc = gW + (size_t)z * DMODEL * DMODEL;

    // Prefetch W chunk 0 (rows 0..127 = 64KB), swizzled. 512 threads.
#pragma unroll
    for (int it = 0; it < 8; it++) {
        int idx = tid + it * 512;
        int r = idx >> 5, u2 = idx & 31;
        cp16(sb + QOFF_WB + r * 512 + ((u2 ^ (r & 7)) << 4), Wsrc + r * 256 + u2 * 8);
    }
    CP_COMMIT();

    // Convert X tile [128 x 256] fp32 -> fp16 hi/lo, swizzled. 512 threads.
#pragma unroll
    for (int it = 0; it < 8; it++) {
        int idx = tid + it * 512;
        int r = idx >> 5, u2 = idx & 31;
        const float4 a = *(const float4*)(X + (size_t)(m0 + r) * DMODEL + u2 * 8);
        const float4 b = *(const float4*)(X + (size_t)(m0 + r) * DMODEL + u2 * 8 + 4);
        __half hh[8];
        hh[0] = __float2half(a.x); hh[1] = __float2half(a.y);
        hh[2] = __float2half(a.z); hh[3] = __float2half(a.w);
        hh[4] = __float2half(b.x); hh[5] = __float2half(b.y);
        hh[6] = __float2half(b.z); hh[7] = __float2half(b.w);
        __half ll[8];
        ll[0] = __float2half(a.x - __half2float(hh[0]));
        ll[1] = __float2half(a.y - __half2float(hh[1]));
        ll[2] = __float2half(a.z - __half2float(hh[2]));
        ll[3] = __float2half(a.w - __half2float(hh[3]));
        ll[4] = __float2half(b.x - __half2float(hh[4]));
        ll[5] = __float2half(b.y - __half2float(hh[5]));
        ll[6] = __float2half(b.z - __half2float(hh[6]));
        ll[7] = __float2half(b.w - __half2float(hh[7]));
        int d = r * 512 + ((u2 ^ (r & 7)) << 4);
        *(float4*)(smem + QOFF_XH + d) = *(float4*)hh;
        *(float4*)(smem + QOFF_XL + d) = *(float4*)ll;
    }

    const int b3 = (lane >> 3) & 1;
    const int l4 = lane >> 4;
    const int rowA = 16 * rg + (lane & 7) + b3 * 8;    // 0..127
    const int ra7 = rowA & 7;
    const uint32_t xhb = sb + QOFF_XH + rowA * 512;
    const uint32_t xlb = sb + QOFF_XL + rowA * 512;
    const int rbB = 8 * l4 + (lane & 7);
    const int rb7 = rbB & 7;
    const uint32_t wbb = sb + QOFF_WB + (h * 64 + rbB) * 512;   // 0..127 rows

    const float scale = (z == 0) ? 0.0625f : 1.0f;
    __half* dst = (z == 0) ? gQ : ((z == 1) ? gKh : gV);
    const int r0 = m0 + 16 * rg + g, r1 = r0 + 8;

#pragma unroll 1
    for (int c = 0; c < 2; c++) {
        CP_WAIT0();
        __syncthreads();

        float sa[8][4];
#pragma unroll
        for (int i = 0; i < 8; i++)
#pragma unroll
            for (int j = 0; j < 4; j++) sa[i][j] = 0.f;

#pragma unroll
        for (int kt = 0; kt < 16; kt++) {
            uint32_t aH[4], aL[4];
            const uint32_t qoff = (((2 * kt + l4) ^ ra7) << 4);
            ldmx4(xhb + qoff, aH);
            ldmx4(xlb + qoff, aL);
            const uint32_t koff = (((2 * kt + b3) ^ rb7) << 4);
            uint32_t wf[4][4];
#pragma unroll
            for (int ntp = 0; ntp < 4; ntp++)
                ldmx4(wbb + ntp * 8192 + koff, wf[ntp]);
#pragma unroll
            for (int ntp = 0; ntp < 4; ntp++) {
                mma16816h(sa[2 * ntp],     aH, wf[ntp][0], wf[ntp][1]);
                mma16816h(sa[2 * ntp + 1], aH, wf[ntp][2], wf[ntp][3]);
            }
#pragma unroll
            for (int ntp = 0; ntp < 4; ntp++) {
                mma16816h(sa[2 * ntp],     aL, wf[ntp][0], wf[ntp][1]);
                mma16816h(sa[2 * ntp + 1], aL, wf[ntp][2], wf[ntp][3]);
            }
        }

        __syncthreads();
        if (c == 0) {
#pragma unroll
            for (int it = 0; it < 8; it++) {
                int idx = tid + it * 512;
                int r = idx >> 5, u2 = idx & 31;
                cp16(sb + QOFF_WB + r * 512 + ((u2 ^ (r & 7)) << 4),
                     Wsrc + (128 + r) * 256 + u2 * 8);
            }
            CP_COMMIT();
        }

#pragma unroll
        for (int i = 0; i < 8; i++) {
            const int col = c * 128 + h * 64 + 8 * i + 2 * t4;
            *(uint32_t*)(dst + (size_t)r0 * DMODEL + col) = pack_f16(sa[i][0] * scale, sa[i][1] * scale);
            *(uint32_t*)(dst + (size_t)r1 * DMODEL + col) = pack_f16(sa[i][2] * scale, sa[i][3] * scale);
        }
    }
}

// ---------------------------------------------------------------------------
// Flash attention (proven R12): FA2 warp split, one full barrier per unit,
// pairwise named barrier for P, 2-slot K/V cp.async rings, C=0 softmax.
// SMEM: Q[64K] K0/K1[32K x2] V0/V1[32K x2] P[16K] = 208KB. 1 CTA/SM.
// ---------------------------------------------------------------------------
#define OFF_Q  0
#define OFF_K0 65536
#define OFF_K1 98304
#define OFF_V0 131072
#define OFF_V1 163840
#define OFF_P  196608
#define FLASH_SMEM 212992

// Fill a 64-key slot (single fp16 plane, 64 rows x 512B). 512 threads.
__device__ __forceinline__ void fill_plane64(const __half* __restrict__ sH,
                                             uint32_t dbuf, int tid) {
#pragma unroll
    for (int it = 0; it < 4; it++) {
        int idx = tid + it * 512;
        int r = idx >> 5, u2 = idx & 31;
        cp16(dbuf + r * 512 + ((u2 ^ (r & 7)) << 4), sH + r * 256 + u2 * 8);
    }
}

__global__ void __launch_bounds__(512, 1)
flash_mma_kernel(const void* __restrict__ mask) {
    extern __shared__ char smem[];
    const int tid = threadIdx.x;
    const int w = tid >> 5, lane = tid & 31;
    const int g = lane >> 2, t4 = lane & 3;
    const int rg = w & 7;        // row group: rows 16*rg .. 16*rg+15
    const int h  = w >> 3;       // key-half (S) / d-half (PV)

    // map blockIdx -> (rt, split); longest row-tiles first
    int rt = 0, s = 0, nsp = 1;
    {
        int acc = 0;
        const int bx = blockIdx.x;
#pragma unroll 1
        for (int m = 63; m >= 0; m--) {
            int n = nsplits(m);
            if (bx < acc + n) { rt = m; s = bx - acc; nsp = n; break; }
            acc += n;
        }
    }
    const int U  = 2 * (rt + 1);                // 64-key units in this row-tile
    const int u0 = (U * s) / nsp;
    const int u1 = (U * (s + 1)) / nsp;
    const int m0 = rt * 128;
    const int pidx = blockIdx.x;                // dense partial slot

    const int kind = g_mask_kind;
    const uint32_t sb = smem_to_u32(smem);
    const uint32_t kslot[2] = {sb + OFF_K0, sb + OFF_K1};
    const uint32_t vslot[2] = {sb + OFF_V0, sb + OFF_V1};

    // Prologue: prefetch K(u0), V(u0), then stage Q under them.
    fill_plane64(gKh + (size_t)(u0 * 64) * DMODEL, kslot[u0 & 1], tid);
    CP_COMMIT();
    fill_plane64(gV + (size_t)(u0 * 64) * DMODEL, vslot[u0 & 1], tid);
    CP_COMMIT();

    // Persistent Q tile (fp16, pre-scaled), swizzled, via LDG+STS
#pragma unroll
    for (int it = 0; it < 8; it++) {
        int idx = tid + it * 512;
        int r = idx >> 5, u2 = idx & 31;
        int d = r * 512 + ((u2 ^ (r & 7)) << 4);
        *(float4*)(smem + OFF_Q + d) = *(const float4*)(gQ + (size_t)(m0 + r) * DMODEL + u2 * 8);
    }

    // per-lane ldmatrix geometry
    const int b3 = (lane >> 3) & 1;
    const int l4 = lane >> 4;
    const int rowA = 16 * rg + (lane & 7) + b3 * 8;    // Q rows (fixed per lane)
    const int ra7 = rowA & 7;
    const uint32_t qb = sb + OFF_Q + rowA * 512;
    const int rbB = 8 * l4 + (lane & 7);               // K row base (16-key group)
    const int rb7 = rbB & 7;
    const int rvB = (lane & 7) + 8 * b3;               // V row base (16-key group)
    const int rv7 = rvB & 7;
    const int prow = (lane & 7) + 8 * b3;              // P row base (PV A-frag)
    const uint32_t pldb = sb + OFF_P + rg * 2048 + prow * 128;

    const int grow0 = m0 + 16 * rg + g;
    const int grow1 = grow0 + 8;

    float o[16][4];
#pragma unroll
    for (int i = 0; i < 16; i++)
#pragma unroll
        for (int j = 0; j < 4; j++) o[i][j] = 0.f;
    float l0 = 0.f, l1 = 0.f;

    for (int u = u0; u < u1; u++) {
        const int j0 = u * 64;
        const int jn = (u + 1 < u1) ? (u + 1) * 64 : j0;   // clamped prefetch
        const int slot = u & 1, nslot = slot ^ 1;

        CP_WAIT0();                            // K(u), V(u) landed (own groups)
        __syncthreads();                       // fills visible + PV(u-1) done

        fill_plane64(gKh + (size_t)jn * DMODEL, kslot[nslot], tid);
        CP_COMMIT();
        fill_plane64(gV + (size_t)jn * DMODEL, vslot[nslot], tid);
        CP_COMMIT();

        // mask prefetch for this warp's 32 keys
        float2 ma0[4], ma1[4];
#pragma unroll
        for (int nt = 0; nt < 4; nt++) {
            const int col = j0 + 32 * h + 8 * nt + 2 * t4;
            ma0[nt] = read_mask2(mask, kind, (size_t)grow0 * NSEQ + col);
            ma1[nt] = read_mask2(mask, kind, (size_t)grow1 * NSEQ + col);
        }

        // ---- S: 16 rows x this warp's 32-key half ----
        const uint32_t khb = kslot[slot] + rbB * 512;
        float sa[4][4];
#pragma unroll
        for (int i = 0; i < 4; i++)
#pragma unroll
            for (int j = 0; j < 4; j++) sa[i][j] = 0.f;

#pragma unroll
        for (int kt = 0; kt < 16; kt++) {
            uint32_t aH[4];
            ldmx4(qb + (((2 * kt + l4) ^ ra7) << 4), aH);
            const uint32_t koff = (((2 * kt + b3) ^ rb7) << 4);
#pragma unroll
            for (int ntp = 0; ntp < 2; ntp++) {
                uint32_t bH[4];
                ldmx4(khb + (2 * h + ntp) * 8192 + koff, bH);
                mma16816h(sa[2 * ntp],     aH, bH[0], bH[1]);
                mma16816h(sa[2 * ntp + 1], aH, bH[2], bH[3]);
            }
        }

        // ---- softmax (C=0) + causal + dropout -> P store to smem ----
#pragma unroll
        for (int nt = 0; nt < 4; nt++) {
            const int col = j0 + 32 * h + 8 * nt + 2 * t4;
            float p0 = (col     <= grow0) ? __expf(sa[nt][0]) : 0.f;
            float p1 = (col + 1 <= grow0) ? __expf(sa[nt][1]) : 0.f;
            float p2 = (col     <= grow1) ? __expf(sa[nt][2]) : 0.f;
            float p3 = (col + 1 <= grow1) ? __expf(sa[nt][3]) : 0.f;
            l0 += p0 + p1;
            l1 += p2 + p3;
            p0 *= ma0[nt].x; p1 *= ma0[nt].y; p2 *= ma1[nt].x; p3 *= ma1[nt].y;
            const int chunk = 2 * (2 * h + (nt >> 1)) + (nt & 1);
            const int addr = OFF_P + rg * 2048 + g * 128 + ((chunk ^ g) << 4) + 4 * t4;
            *(uint32_t*)(smem + addr)        = pack_f16(p0, p1);   // row g
            *(uint32_t*)(smem + addr + 1024) = pack_f16(p2, p3);   // row g+8
        }
        BAR_PAIR(1 + rg);                      // only the 2 warps of this rg

        // ---- PV: all 64 keys, this warp's 128-wide d-half ----
        const uint32_t vhb = vslot[slot] + rvB * 512;
#pragma unroll
        for (int kt = 0; kt < 4; kt++) {
            uint32_t pf[4];
            ldmx4(pldb + (((2 * kt + l4) ^ (prow & 7)) << 4), pf);
            const uint32_t krow = kt * 8192;
#pragma unroll
            for (int ntp = 0; ntp < 8; ntp++) {
                const uint32_t voff = krow + (((16 * h + 2 * ntp + l4) ^ rv7) << 4);
                uint32_t bH[4];
                ldmx4t(vhb + voff, bH);
                mma16816h(o[2 * ntp],     pf, bH[0], bH[1]);
                mma16816h(o[2 * ntp + 1], pf, bH[2], bH[3]);
            }
        }
    }

    CP_WAIT0();                                // drain dangling prefetches

    // ---- epilogue: unnormalized partial O + l (per key-half slot) ----
    l0 += __shfl_xor_sync(0xFFFFFFFFu, l0, 1);
    l0 += __shfl_xor_sync(0xFFFFFFFFu, l0, 2);
    l1 += __shfl_xor_sync(0xFFFFFFFFu, l1, 1);
    l1 += __shfl_xor_sync(0xFFFFFFFFu, l1, 2);
    if (t4 == 0) {
        g_lpart[(pidx * 2 + h) * 128 + 16 * rg + g]     = l0;
        g_lpart[(pidx * 2 + h) * 128 + 16 * rg + 8 + g] = l1;
    }

    float* Op = g_Opart + (size_t)pidx * 128 * 256;
    const int r0 = 16 * rg + g, r1 = r0 + 8;
#pragma unroll
    for (int nt = 0; nt < 16; nt++) {
        const int col = 128 * h + 8 * nt + 2 * t4;
        *(float2*)(Op + r0 * 256 + col) = make_float2(o[nt][0], o[nt][1]);
        *(float2*)(Op + r1 * 256 + col) = make_float2(o[nt][2], o[nt][3]);
    }
}

// ---------------------------------------------------------------------------
// Reduce: out = 2 * sum(O_s) / sum(l_s,h). Grid 1024 (8 rows/CTA).
// ---------------------------------------------------------------------------
__global__ void __launch_bounds__(256)
reduce_kernel(float* __restrict__ out) {
    const int rt  = blockIdx.x >> 4;
    const int sub = blockIdx.x & 15;
    const int nsp = nsplits(rt);
    int base = 0;
#pragma unroll 1
    for (int m = 63; m > rt; m--) base += nsplits(m);

#pragma unroll
    for (int it = 0; it < 2; it++) {
        int idx = threadIdx.x + it * 256;           // 512 float4 cells: 8 rows x 64
        int r = sub * 8 + (idx >> 6), c4 = idx & 63;
        float4 acc = make_float4(0.f, 0.f, 0.f, 0.f);
        float lsum = 0.f;
#pragma unroll 1
        for (int sp = 0; sp < nsp; sp++) {
            lsum += g_lpart[((base + sp) * 2) * 128 + r]
                  + g_lpart[((base + sp) * 2 + 1) * 128 + r];
            float4 ov = *(const float4*)&g_Opart[((size_t)(base + sp) * 128 + r) * 256 + c4 * 4];
            acc.x += ov.x; acc.y += ov.y; acc.z += ov.z; acc.w += ov.w;
        }
        float inv = 2.0f / lsum;
        float4 wv = make_float4(acc.x * inv, acc.y * inv, acc.z * inv, acc.w * inv);
        *(float4*)&out[((size_t)(rt * 128 + r)) * 256 + c4 * 4] = wv;
    }
}

// ---------------------------------------------------------------------------
extern "C" void kernel_launch(void* const* d_in, const int* in_sizes, int n_in,
                              void* d_out, int out_size) {
    (void)in_sizes; (void)n_in; (void)out_size;
    const float* X  = (const float*)d_in[0];
    const float* Wq = (const float*)d_in[1];
    const float* Wk = (const float*)d_in[2];
    const float* Wv = (const float*)d_in[3];
    const void*  mask = d_in[4];
    float* out = (float*)d_out;

    w_convert_kernel<<<3, 256>>>(Wq, Wk, Wv, (const unsigned int*)mask);

    cudaFuncSetAttribute(qkv_tc_kernel, cudaFuncAttributeMaxDynamicSharedMemorySize,
                         QKV_SMEM);
    dim3 gq(NSEQ / 128, 3);
    qkv_tc_kernel<<<gq, 512, QKV_SMEM>>>(X);

    cudaFuncSetAttribute(flash_mma_kernel, cudaFuncAttributeMaxDynamicSharedMemorySize,
                         FLASH_SMEM);
    flash_mma_kernel<<<GRID_FLASH, 512, FLASH_SMEM>>>(mask);

    reduce_kernel<<<1024, 256>>>(out);
}

// round 17
// speedup vs baseline: 1.0112x; 1.0112x over previous
#include <cuda_runtime.h>
#include <cuda_bf16.h>
#include <cuda_fp16.h>
#include <math.h>
#include <stdint.h>

#define NSEQ 8192
#define DMODEL 256

typedef unsigned long long u64;

// ---------------------------------------------------------------------------
// Warp-level tensor-core + cp.async primitives (sm_80+, valid for sm_103 PTX)
// ---------------------------------------------------------------------------
__device__ __forceinline__ uint32_t smem_to_u32(const void* p) {
    uint32_t a;
    asm("{ .reg .u64 t; cvta.to.shared.u64 t, %1; cvt.u32.u64 %0, t; }" : "=r"(a) : "l"(p));
    return a;
}
__device__ __forceinline__ void ldmx4(uint32_t addr, uint32_t r[4]) {
    asm volatile("ldmatrix.sync.aligned.m8n8.x4.shared.b16 {%0,%1,%2,%3}, [%4];"
                 : "=r"(r[0]), "=r"(r[1]), "=r"(r[2]), "=r"(r[3]) : "r"(addr));
}
__device__ __forceinline__ void ldmx4t(uint32_t addr, uint32_t r[4]) {
    asm volatile("ldmatrix.sync.aligned.m8n8.x4.trans.shared.b16 {%0,%1,%2,%3}, [%4];"
                 : "=r"(r[0]), "=r"(r[1]), "=r"(r[2]), "=r"(r[3]) : "r"(addr));
}
// fp16 MMA, fp32 accum
__device__ __forceinline__ void mma16816h(float* c, const uint32_t* a, uint32_t b0, uint32_t b1) {
    asm volatile(
        "mma.sync.aligned.m16n8k16.row.col.f32.f16.f16.f32 "
        "{%0,%1,%2,%3},{%4,%5,%6,%7},{%8,%9},{%0,%1,%2,%3};"
        : "+f"(c[0]), "+f"(c[1]), "+f"(c[2]), "+f"(c[3])
        : "r"(a[0]), "r"(a[1]), "r"(a[2]), "r"(a[3]), "r"(b0), "r"(b1));
}
__device__ __forceinline__ uint32_t pack_f16(float lo, float hi) {
    uint32_t r;
    asm("cvt.rn.f16x2.f32 %0, %1, %2;" : "=r"(r) : "f"(hi), "f"(lo));
    return r;
}
__device__ __forceinline__ void cp16(uint32_t dst, const void* src) {
    asm volatile("cp.async.cg.shared.global [%0], [%1], 16;" :: "r"(dst), "l"(src) : "memory");
}
#define CP_COMMIT()  asm volatile("cp.async.commit_group;" ::: "memory")
#define CP_WAIT0()   asm volatile("cp.async.wait_group 0;" ::: "memory")
#define BAR_PAIR(id) asm volatile("bar.sync %0, 64;" :: "r"(id) : "memory")

// ---------------------------------------------------------------------------
// Schedule: splits per row-tile; sum over rt=0..63 equals 296 = 2 x 148 SMs.
// ---------------------------------------------------------------------------
__host__ __device__ __forceinline__ int nsplits(int rt) { return ((rt + 1) >> 3) + 1; }
#define GRID_FLASH 296

// ---------------------------------------------------------------------------
// Device globals (no allocs allowed)
// ---------------------------------------------------------------------------
__device__ __half gQ [NSEQ * DMODEL];                // fp16, pre-scaled by 1/16
__device__ __half gKh[NSEQ * DMODEL];                // single fp16 plane
__device__ __half gV [NSEQ * DMODEL];                // single fp16 plane
__device__ __half gW [3 * DMODEL * DMODEL];          // fp16 weights (z-major)
__device__ __half gOp[GRID_FLASH * 128 * 256];       // fp16 O partials (dense)
__device__ float g_lpart[GRID_FLASH * 2 * 128];      // 2 key-half slots per CTA
__device__ int   g_mask_kind;

// Read 2 consecutive mask values at even element index.
__device__ __forceinline__ float2 read_mask2(const void* m, int kind, size_t idx) {
    float2 r;
    if (kind == 0) {
        float2 v = *(const float2*)((const float*)m + idx);
        r.x = (v.x != 0.f) ? 1.f : 0.f; r.y = (v.y != 0.f) ? 1.f : 0.f;
    } else if (kind == 2) {
        unsigned short v = *(const unsigned short*)((const unsigned char*)m + idx);
        r.x = (v & 0xFFu) ? 1.f : 0.f; r.y = (v >> 8) ? 1.f : 0.f;
    } else if (kind == 1) {
        int2 v = *(const int2*)((const int*)m + idx);
        r.x = (v.x != 0) ? 1.f : 0.f; r.y = (v.y != 0) ? 1.f : 0.f;
    } else {
        unsigned v = *(const unsigned*)((const unsigned short*)m + idx);
        r.x = (v & 0xFFFFu) ? 1.f : 0.f; r.y = (v >> 16) ? 1.f : 0.f;
    }
    return r;
}

// ---------------------------------------------------------------------------
// Weight conversion + mask dtype detection fused (block 0 detects first).
// ---------------------------------------------------------------------------
__global__ void __launch_bounds__(256)
w_convert_kernel(const float* __restrict__ Wq, const float* __restrict__ Wk,
                 const float* __restrict__ Wv, const unsigned int* __restrict__ mw) {
    if (blockIdx.x == 0) {
        __shared__ int flags;
        if (threadIdx.x == 0) flags = 0;
        __syncthreads();
        int f = 0;
        for (int i = threadIdx.x; i < 2048; i += blockDim.x) {
            unsigned v = mw[i];
            if (v == 0u) continue;
            if (v == 0x3F803F80u || v == 0x00003F80u) f |= 2;
            else if (v == 0x3C003C00u || v == 0x00003C00u || v == 0x3C000000u) f |= 2;
            else if (v == 0x3F800000u) f |= 1;
            else if (v == 1u) f |= 8;
            else f |= 4;
        }
        atomicOr(&flags, f);
        __syncthreads();
        if (threadIdx.x == 0) {
            int fl = flags, kind;
            if      (fl & 2) kind = 3;      // 16-bit
            else if (fl & 1) kind = 0;      // f32
            else if (fl & 4) kind = 2;      // u8
            else if (fl & 8) kind = 1;      // i32
            else             kind = 0;
            g_mask_kind = kind;
        }
    }

    const int z = blockIdx.x;
    const float* W = (z == 0) ? Wq : ((z == 1) ? Wk : Wv);
    __half* dst = gW + (size_t)z * DMODEL * DMODEL;
    for (int i = threadIdx.x; i < DMODEL * DMODEL / 4; i += 256) {
        float4 v = *(const float4*)(W + i * 4);
        *(uint32_t*)(dst + i * 4)     = pack_f16(v.x, v.y);
        *(uint32_t*)(dst + i * 4 + 2) = pack_f16(v.z, v.w);
    }
}

// ---------------------------------------------------------------------------
// Tensor-core QKV (proven R15/R12): C[128 x 256] = (Xh + Xl) @ W^T.
// SMEM: XH[64K] XL[64K] WB[64K] = 192KB. grid (64, 3), 256 thr, 1 CTA/SM.
// ---------------------------------------------------------------------------
#define QOFF_XH 0
#define QOFF_XL 65536
#define QOFF_WB 131072
#define QKV_SMEM 196608

__global__ void __launch_bounds__(256, 1)
qkv_tc_kernel(const float* __restrict__ X) {
    extern __shared__ char smem[];
    const int tid = threadIdx.x;
    const int w = tid >> 5, lane = tid & 31;
    const int g = lane >> 2, t4 = lane & 3;
    const int m0 = blockIdx.x * 128;
    const int z = blockIdx.y;
    const uint32_t sb = smem_to_u32(smem);

    const __half* Wsrc = gW + (size_t)z * DMODEL * DMODEL;

#pragma unroll
    for (int it = 0; it < 16; it++) {
        int idx = tid + it * 256;
        int r = idx >> 5, u2 = idx & 31;
        cp16(sb + QOFF_WB + r * 512 + ((u2 ^ (r & 7)) << 4), Wsrc + r * 256 + u2 * 8);
    }
    CP_COMMIT();

#pragma unroll
    for (int it = 0; it < 16; it++) {
        int idx = tid + it * 256;
        int r = idx >> 5, u2 = idx & 31;
        const float4 a = *(const float4*)(X + (size_t)(m0 + r) * DMODEL + u2 * 8);
        const float4 b = *(const float4*)(X + (size_t)(m0 + r) * DMODEL + u2 * 8 + 4);
        __half hh[8];
        hh[0] = __float2half(a.x); hh[1] = __float2half(a.y);
        hh[2] = __float2half(a.z); hh[3] = __float2half(a.w);
        hh[4] = __float2half(b.x); hh[5] = __float2half(b.y);
        hh[6] = __float2half(b.z); hh[7] = __float2half(b.w);
        __half ll[8];
        ll[0] = __float2half(a.x - __half2float(hh[0]));
        ll[1] = __float2half(a.y - __half2float(hh[1]));
        ll[2] = __float2half(a.z - __half2float(hh[2]));
        ll[3] = __float2half(a.w - __half2float(hh[3]));
        ll[4] = __float2half(b.x - __half2float(hh[4]));
        ll[5] = __float2half(b.y - __half2float(hh[5]));
        ll[6] = __float2half(b.z - __half2float(hh[6]));
        ll[7] = __float2half(b.w - __half2float(hh[7]));
        int d = r * 512 + ((u2 ^ (r & 7)) << 4);
        *(float4*)(smem + QOFF_XH + d) = *(float4*)hh;
        *(float4*)(smem + QOFF_XL + d) = *(float4*)ll;
    }

    const int b3 = (lane >> 3) & 1;
    const int l4 = lane >> 4;
    const int rowA = 16 * w + (lane & 7) + b3 * 8;
    const int ra7 = rowA & 7;
    const uint32_t xhb = sb + QOFF_XH + rowA * 512;
    const uint32_t xlb = sb + QOFF_XL + rowA * 512;
    const int rbB = 8 * l4 + (lane & 7);
    const int rb7 = rbB & 7;
    const uint32_t wbb = sb + QOFF_WB + rbB * 512;

    const float scale = (z == 0) ? 0.0625f : 1.0f;
    __half* dst = (z == 0) ? gQ : ((z == 1) ? gKh : gV);
    const int r0 = m0 + 16 * w + g, r1 = r0 + 8;

#pragma unroll 1
    for (int c = 0; c < 2; c++) {
        CP_WAIT0();
        __syncthreads();

        float sa[16][4];
#pragma unroll
        for (int i = 0; i < 16; i++)
#pragma unroll
            for (int j = 0; j < 4; j++) sa[i][j] = 0.f;

#pragma unroll
        for (int kt = 0; kt < 16; kt++) {
            uint32_t aH[4], aL[4];
            const uint32_t qoff = (((2 * kt + l4) ^ ra7) << 4);
            ldmx4(xhb + qoff, aH);
            ldmx4(xlb + qoff, aL);
            const uint32_t koff = (((2 * kt + b3) ^ rb7) << 4);
            uint32_t wf[8][4];
#pragma unroll
            for (int ntp = 0; ntp < 8; ntp++)
                ldmx4(wbb + ntp * 8192 + koff, wf[ntp]);
#pragma unroll
            for (int ntp = 0; ntp < 8; ntp++) {
                mma16816h(sa[2 * ntp],     aH, wf[ntp][0], wf[ntp][1]);
                mma16816h(sa[2 * ntp + 1], aH, wf[ntp][2], wf[ntp][3]);
            }
#pragma unroll
            for (int ntp = 0; ntp < 8; ntp++) {
                mma16816h(sa[2 * ntp],     aL, wf[ntp][0], wf[ntp][1]);
                mma16816h(sa[2 * ntp + 1], aL, wf[ntp][2], wf[ntp][3]);
            }
        }

        __syncthreads();
        if (c == 0) {
#pragma unroll
            for (int it = 0; it < 16; it++) {
                int idx = tid + it * 256;
                int r = idx >> 5, u2 = idx & 31;
                cp16(sb + QOFF_WB + r * 512 + ((u2 ^ (r & 7)) << 4),
                     Wsrc + (128 + r) * 256 + u2 * 8);
            }
            CP_COMMIT();
        }

#pragma unroll
        for (int i = 0; i < 16; i++) {
            const int col = c * 128 + 8 * i + 2 * t4;
            *(uint32_t*)(dst + (size_t)r0 * DMODEL + col) = pack_f16(sa[i][0] * scale, sa[i][1] * scale);
            *(uint32_t*)(dst + (size_t)r1 * DMODEL + col) = pack_f16(sa[i][2] * scale, sa[i][3] * scale);
        }
    }
}

// ---------------------------------------------------------------------------
// Flash attention (proven R12/R15): FA2 warp split, one full barrier per
// unit, pairwise named barrier for P, 2-slot K/V cp.async rings, C=0
// softmax. Epilogue now writes fp16 O partials (halved gmem traffic).
// SMEM: Q[64K] K0/K1[32K x2] V0/V1[32K x2] P[16K] = 208KB. 1 CTA/SM.
// ---------------------------------------------------------------------------
#define OFF_Q  0
#define OFF_K0 65536
#define OFF_K1 98304
#define OFF_V0 131072
#define OFF_V1 163840
#define OFF_P  196608
#define FLASH_SMEM 212992

// Fill a 64-key slot (single fp16 plane, 64 rows x 512B). 512 threads.
__device__ __forceinline__ void fill_plane64(const __half* __restrict__ sH,
                                             uint32_t dbuf, int tid) {
#pragma unroll
    for (int it = 0; it < 4; it++) {
        int idx = tid + it * 512;
        int r = idx >> 5, u2 = idx & 31;
        cp16(dbuf + r * 512 + ((u2 ^ (r & 7)) << 4), sH + r * 256 + u2 * 8);
    }
}

__global__ void __launch_bounds__(512, 1)
flash_mma_kernel(const void* __restrict__ mask) {
    extern __shared__ char smem[];
    const int tid = threadIdx.x;
    const int w = tid >> 5, lane = tid & 31;
    const int g = lane >> 2, t4 = lane & 3;
    const int rg = w & 7;        // row group: rows 16*rg .. 16*rg+15
    const int h  = w >> 3;       // key-half (S) / d-half (PV)

    // map blockIdx -> (rt, split); longest row-tiles first
    int rt = 0, s = 0, nsp = 1;
    {
        int acc = 0;
        const int bx = blockIdx.x;
#pragma unroll 1
        for (int m = 63; m >= 0; m--) {
            int n = nsplits(m);
            if (bx < acc + n) { rt = m; s = bx - acc; nsp = n; break; }
            acc += n;
        }
    }
    const int U  = 2 * (rt + 1);                // 64-key units in this row-tile
    const int u0 = (U * s) / nsp;
    const int u1 = (U * (s + 1)) / nsp;
    const int m0 = rt * 128;
    const int pidx = blockIdx.x;                // dense partial slot

    const int kind = g_mask_kind;
    const uint32_t sb = smem_to_u32(smem);
    const uint32_t kslot[2] = {sb + OFF_K0, sb + OFF_K1};
    const uint32_t vslot[2] = {sb + OFF_V0, sb + OFF_V1};

    // Prologue: prefetch K(u0), V(u0), then stage Q under them.
    fill_plane64(gKh + (size_t)(u0 * 64) * DMODEL, kslot[u0 & 1], tid);
    CP_COMMIT();
    fill_plane64(gV + (size_t)(u0 * 64) * DMODEL, vslot[u0 & 1], tid);
    CP_COMMIT();

    // Persistent Q tile (fp16, pre-scaled), swizzled, via LDG+STS
#pragma unroll
    for (int it = 0; it < 8; it++) {
        int idx = tid + it * 512;
        int r = idx >> 5, u2 = idx & 31;
        int d = r * 512 + ((u2 ^ (r & 7)) << 4);
        *(float4*)(smem + OFF_Q + d) = *(const float4*)(gQ + (size_t)(m0 + r) * DMODEL + u2 * 8);
    }

    // per-lane ldmatrix geometry
    const int b3 = (lane >> 3) & 1;
    const int l4 = lane >> 4;
    const int rowA = 16 * rg + (lane & 7) + b3 * 8;    // Q rows (fixed per lane)
    const int ra7 = rowA & 7;
    const uint32_t qb = sb + OFF_Q + rowA * 512;
    const int rbB = 8 * l4 + (lane & 7);               // K row base (16-key group)
    const int rb7 = rbB & 7;
    const int rvB = (lane & 7) + 8 * b3;               // V row base (16-key group)
    const int rv7 = rvB & 7;
    const int prow = (lane & 7) + 8 * b3;              // P row base (PV A-frag)
    const uint32_t pldb = sb + OFF_P + rg * 2048 + prow * 128;

    const int grow0 = m0 + 16 * rg + g;
    const int grow1 = grow0 + 8;

    float o[16][4];
#pragma unroll
    for (int i = 0; i < 16; i++)
#pragma unroll
        for (int j = 0; j < 4; j++) o[i][j] = 0.f;
    float l0 = 0.f, l1 = 0.f;

    for (int u = u0; u < u1; u++) {
        const int j0 = u * 64;
        const int jn = (u + 1 < u1) ? (u + 1) * 64 : j0;   // clamped prefetch
        const int slot = u & 1, nslot = slot ^ 1;

        CP_WAIT0();                            // K(u), V(u) landed (own groups)
        __syncthreads();                       // fills visible + PV(u-1) done

        fill_plane64(gKh + (size_t)jn * DMODEL, kslot[nslot], tid);
        CP_COMMIT();
        fill_plane64(gV + (size_t)jn * DMODEL, vslot[nslot], tid);
        CP_COMMIT();

        // mask prefetch for this warp's 32 keys
        float2 ma0[4], ma1[4];
#pragma unroll
        for (int nt = 0; nt < 4; nt++) {
            const int col = j0 + 32 * h + 8 * nt + 2 * t4;
            ma0[nt] = read_mask2(mask, kind, (size_t)grow0 * NSEQ + col);
            ma1[nt] = read_mask2(mask, kind, (size_t)grow1 * NSEQ + col);
        }

        // ---- S: 16 rows x this warp's 32-key half ----
        const uint32_t khb = kslot[slot] + rbB * 512;
        float sa[4][4];
#pragma unroll
        for (int i = 0; i < 4; i++)
#pragma unroll
            for (int j = 0; j < 4; j++) sa[i][j] = 0.f;

#pragma unroll
        for (int kt = 0; kt < 16; kt++) {
            uint32_t aH[4];
            ldmx4(qb + (((2 * kt + l4) ^ ra7) << 4), aH);
            const uint32_t koff = (((2 * kt + b3) ^ rb7) << 4);
#pragma unroll
            for (int ntp = 0; ntp < 2; ntp++) {
                uint32_t bH[4];
                ldmx4(khb + (2 * h + ntp) * 8192 + koff, bH);
                mma16816h(sa[2 * ntp],     aH, bH[0], bH[1]);
                mma16816h(sa[2 * ntp + 1], aH, bH[2], bH[3]);
            }
        }

        // ---- softmax (C=0) + causal + dropout -> P store to smem ----
#pragma unroll
        for (int nt = 0; nt < 4; nt++) {
            const int col = j0 + 32 * h + 8 * nt + 2 * t4;
            float p0 = (col     <= grow0) ? __expf(sa[nt][0]) : 0.f;
            float p1 = (col + 1 <= grow0) ? __expf(sa[nt][1]) : 0.f;
            float p2 = (col     <= grow1) ? __expf(sa[nt][2]) : 0.f;
            float p3 = (col + 1 <= grow1) ? __expf(sa[nt][3]) : 0.f;
            l0 += p0 + p1;
            l1 += p2 + p3;
            p0 *= ma0[nt].x; p1 *= ma0[nt].y; p2 *= ma1[nt].x; p3 *= ma1[nt].y;
            const int chunk = 2 * (2 * h + (nt >> 1)) + (nt & 1);
            const int addr = OFF_P + rg * 2048 + g * 128 + ((chunk ^ g) << 4) + 4 * t4;
            *(uint32_t*)(smem + addr)        = pack_f16(p0, p1);   // row g
            *(uint32_t*)(smem + addr + 1024) = pack_f16(p2, p3);   // row g+8
        }
        BAR_PAIR(1 + rg);                      // only the 2 warps of this rg

        // ---- PV: all 64 keys, this warp's 128-wide d-half ----
        const uint32_t vhb = vslot[slot] + rvB * 512;
#pragma unroll
        for (int kt = 0; kt < 4; kt++) {
            uint32_t pf[4];
            ldmx4(pldb + (((2 * kt + l4) ^ (prow & 7)) << 4), pf);
            const uint32_t krow = kt * 8192;
#pragma unroll
            for (int ntp = 0; ntp < 8; ntp++) {
                const uint32_t voff = krow + (((16 * h + 2 * ntp + l4) ^ rv7) << 4);
                uint32_t bH[4];
                ldmx4t(vhb + voff, bH);
                mma16816h(o[2 * ntp],     pf, bH[0], bH[1]);
                mma16816h(o[2 * ntp + 1], pf, bH[2], bH[3]);
            }
        }
    }

    CP_WAIT0();                                // drain dangling prefetches

    // ---- epilogue: fp16 unnormalized partial O + fp32 l ----
    l0 += __shfl_xor_sync(0xFFFFFFFFu, l0, 1);
    l0 += __shfl_xor_sync(0xFFFFFFFFu, l0, 2);
    l1 += __shfl_xor_sync(0xFFFFFFFFu, l1, 1);
    l1 += __shfl_xor_sync(0xFFFFFFFFu, l1, 2);
    if (t4 == 0) {
        g_lpart[(pidx * 2 + h) * 128 + 16 * rg + g]     = l0;
        g_lpart[(pidx * 2 + h) * 128 + 16 * rg + 8 + g] = l1;
    }

    __half* Op = gOp + (size_t)pidx * 128 * 256;
    const int r0 = 16 * rg + g, r1 = r0 + 8;
#pragma unroll
    for (int nt = 0; nt < 16; nt++) {
        const int col = 128 * h + 8 * nt + 2 * t4;
        *(uint32_t*)(Op + r0 * 256 + col) = pack_f16(o[nt][0], o[nt][1]);
        *(uint32_t*)(Op + r1 * 256 + col) = pack_f16(o[nt][2], o[nt][3]);
    }
}

// ---------------------------------------------------------------------------
// Reduce: out = 2 * sum(O_s) / sum(l_s,h). fp16 partial reads (half traffic).
// Grid 1024 (8 rows/CTA).
// ---------------------------------------------------------------------------
__global__ void __launch_bounds__(256)
reduce_kernel(float* __restrict__ out) {
    const int rt  = blockIdx.x >> 4;
    const int sub = blockIdx.x & 15;
    const int nsp = nsplits(rt);
    int base = 0;
#pragma unroll 1
    for (int m = 63; m > rt; m--) base += nsplits(m);

#pragma unroll
    for (int it = 0; it < 2; it++) {
        int idx = threadIdx.x + it * 256;           // 512 float4 cells: 8 rows x 64
        int r = sub * 8 + (idx >> 6), c4 = idx & 63;
        float4 acc = make_float4(0.f, 0.f, 0.f, 0.f);
        float lsum = 0.f;
#pragma unroll 1
        for (int sp = 0; sp < nsp; sp++) {
            lsum += g_lpart[((base + sp) * 2) * 128 + r]
                  + g_lpart[((base + sp) * 2 + 1) * 128 + r];
            const __half2* ov = (const __half2*)&gOp[((size_t)(base + sp) * 128 + r) * 256 + c4 * 4];
            float2 va = __half22float2(ov[0]);
            float2 vb = __half22float2(ov[1]);
            acc.x += va.x; acc.y += va.y; acc.z += vb.x; acc.w += vb.y;
        }
        float inv = 2.0f / lsum;
        float4 wv = make_float4(acc.x * inv, acc.y * inv, acc.z * inv, acc.w * inv);
        *(float4*)&out[((size_t)(rt * 128 + r)) * 256 + c4 * 4] = wv;
    }
}

// ---------------------------------------------------------------------------
extern "C" void kernel_launch(void* const* d_in, const int* in_sizes, int n_in,
                              void* d_out, int out_size) {
    (void)in_sizes; (void)n_in; (void)out_size;
    const float* X  = (const float*)d_in[0];
    const float* Wq = (const float*)d_in[1];
    const float* Wk = (const float*)d_in[2];
    const float* Wv = (const float*)d_in[3];
    const void*  mask = d_in[4];
    float* out = (float*)d_out;

    w_convert_kernel<<<3, 256>>>(Wq, Wk, Wv, (const unsigned int*)mask);

    cudaFuncSetAttribute(qkv_tc_kernel, cudaFuncAttributeMaxDynamicSharedMemorySize,
                         QKV_SMEM);
    dim3 gq(NSEQ / 128, 3);
    qkv_tc_kernel<<<gq, 256, QKV_SMEM>>>(X);

    cudaFuncSetAttribute(flash_mma_kernel, cudaFuncAttributeMaxDynamicSharedMemorySize,
                         FLASH_SMEM);
    flash_mma_kernel<<<GRID_FLASH, 512, FLASH_SMEM>>>(mask);

    reduce_kernel<<<1024, 256>>>(out);
}